// round 13
// baseline (speedup 1.0000x reference)
#include <cuda_runtime.h>
#include <cuda_fp16.h>
#include <cstdint>

// ---------------------------------------------------------------------------
// Round 13: fp16 m16n8k16, M_tile=64, 4 warps (2Mx2N, warp tile 32x64),
// 4 CTAs/SM (41.2KB smem, <=128 regs). Theory: legacy mma rides tcgen05
// datapath with 4-cyc/dispatch floor (M-invariant); R12 runs 5.28 cyc/instr
// because 2 CTAs/SM leave the queue starved 24% of the time. 4 co-resident
// CTAs overlap serial phases -> approach the 495us floor.
// ---------------------------------------------------------------------------

struct Params {
    const float* x;
    const float* w1[5]; const float* b1[5];
    const float* w2[5]; const float* b2[5];
    const float* w3[5]; const float* b3[5];
    float* out;
};

__constant__ int c_gi[21]  = {0,1,1,1,2,2,3,3,3,3,3,3,3,3,3,3,4,4,4,4,4};
__constant__ int c_ki[21]  = {0,0,1,2,0,1,0,1,2,3,4,5,6,7,8,9,0,1,2,3,4};
__constant__ int c_n[21]   = {6,5,5,5,4,4,3,3,3,3,3,3,3,3,3,3,2,2,2,2,2};
__constant__ int c_out[21] = {0,5,9,13,1,17,2,3,6,7,10,11,14,15,18,19,4,8,12,16,20};
__constant__ int c_nb[21][6] = {
    {0,1,5,9,13,17},
    {0,5,6,1,9,0},  {0,9,10,5,13,0}, {0,13,14,9,17,0},
    {0,1,2,5,0,0},  {0,17,18,13,0,0},
    {1,2,3,0,0,0},  {2,3,4,0,0,0},
    {5,6,7,0,0,0},  {6,7,8,0,0,0},
    {9,10,11,0,0,0},{10,11,12,0,0,0},
    {13,14,15,0,0,0},{14,15,16,0,0,0},
    {17,18,19,0,0,0},{18,19,20,0,0,0},
    {3,4,0,0,0,0},  {7,8,0,0,0,0}, {11,12,0,0,0,0},
    {15,16,0,0,0,0},{19,20,0,0,0,0}
};
// per-node half-offset of W1 image (chunks of 8192 halves = one 64-k slab)
__constant__ int c_w1i_off[21] = {
    0,49152,90112,131072,172032,204800,
    237568,262144,286720,311296,335872,360448,385024,409600,434176,458752,
    483328,499712,516096,532480,548864
};

// Pre-shuffled fp16 weight images (exact SMEM byte layout)
__device__ __align__(16) __half g_w1i[565248];
__device__ __align__(16) __half g_w2i[344064];   // 21 * 2 * 8192
__device__ __align__(16) __half g_w3i[172032];   // 21 * 8192

// SMEM map (bytes), M_tile = 64. Tiles: 16 rows x 32B.
#define SM_HA 0                      // 32 tiles * 512 = 16384
#define SM_XA 16384                  // 16 tiles * 528 =  8448
#define SM_WB 24832                  // 16KB W chunk
#define SMEM_TOTAL 41216

__device__ __forceinline__ uint32_t pkh2(float lo, float hi) {
    uint32_t r;   // low half = lo
    asm("cvt.rn.f16x2.f32 %0, %1, %2;" : "=r"(r) : "f"(hi), "f"(lo));
    return r;
}

__device__ __forceinline__ void mma16(float c[4],
                                      uint32_t a0, uint32_t a1, uint32_t a2, uint32_t a3,
                                      uint32_t b0, uint32_t b1) {
    asm volatile(
        "mma.sync.aligned.m16n8k16.row.col.f32.f16.f16.f32 "
        "{%0,%1,%2,%3},{%4,%5,%6,%7},{%8,%9},{%0,%1,%2,%3};"
        : "+f"(c[0]), "+f"(c[1]), "+f"(c[2]), "+f"(c[3])
        : "r"(a0), "r"(a1), "r"(a2), "r"(a3), "r"(b0), "r"(b1));
}
__device__ __forceinline__ void domma(float c[4], uint2 Pg, uint2 Pg8, uint2 Pb) {
    mma16(c, Pg.x, Pg8.x, Pg.y, Pg8.y, Pb.x, Pb.y);
}

#define CP16(dst, src) \
    asm volatile("cp.async.ca.shared.global [%0], [%1], 16;" :: "r"(dst), "l"(src))
#define CP_WAIT() \
    asm volatile("cp.async.commit_group;\ncp.async.wait_group 0;" ::: "memory")

__device__ __forceinline__ uint32_t smem_u32(const void* p) {
    uint32_t a;
    asm("{ .reg .u64 t; cvta.to.shared.u64 t, %1; cvt.u32.u64 %0, t; }"
        : "=r"(a) : "l"(p));
    return a;
}

// ------------------------------ prep kernel --------------------------------
// Identical to R6/R12 (verified): B tile stride = 128 halves.
__device__ __forceinline__ int imgh(int n, int k, int K16, int NK16c) {
    int jw = (k & 15) >> 1, lo = k & 1;
    int rn = n & 7, NB = n >> 3, s = (rn >> 2) & 1;
    return (NB * NK16c + K16) * 128 + rn * 16 +
           ((((jw >> 1) & 1) ^ s) << 3) + ((jw & 1) << 2) + ((jw >> 2) << 1) + lo;
}

__global__ void prep_kernel(Params p) {
    const int node = blockIdx.y;
    const int gi = c_gi[node], ki = c_ki[node], nnb = c_n[node];
    const int i = blockIdx.x * 256 + threadIdx.x;
    if (blockIdx.z == 0) {
        const int K1 = nnb * 64;
        if (i >= 128 * K1) return;
        const int k = i >> 7, n = i & 127;
        float v = p.w1[gi][((size_t)ki * K1 + k) * 128 + n];
        g_w1i[c_w1i_off[node] + (k >> 6) * 8192 + imgh(n, k, (k >> 4) & 3, 4)] =
            __float2half_rn(v);
    } else if (blockIdx.z == 1) {
        if (i >= 16384) return;
        const int k = i >> 7, n = i & 127;
        float v = p.w2[gi][(size_t)ki * 16384 + (size_t)k * 128 + n];
        g_w2i[node * 16384 + (k >> 6) * 8192 + imgh(n, k, (k >> 4) & 3, 4)] =
            __float2half_rn(v);
    } else {
        if (i >= 8192) return;
        const int k = i >> 6, n = i & 63;
        float v = p.w3[gi][(size_t)ki * 8192 + (size_t)k * 64 + n];
        g_w3i[node * 8192 + imgh(n, k, k >> 4, 8)] = __float2half_rn(v);
    }
}

// ------------------------------ main kernel --------------------------------

__global__ __launch_bounds__(128, 4)
void mp13_kernel(Params p) {
    extern __shared__ char smem[];
    const int tid = threadIdx.x;
    const int w = tid >> 5, lane = tid & 31;
    const int g = lane >> 2, t4 = lane & 3;
    const int node = blockIdx.x;
    const int m0 = blockIdx.y * 64;
    const int gi = c_gi[node], ki = c_ki[node], nnb = c_n[node];
    const int wm = w & 1, wn = w >> 1;          // 2M x 2N grid of 32x64 tiles
    const int sg = (g >> 2) & 1;
    const int awl  = (((t4 >> 1) ^ sg) << 4) + ((t4 & 1) << 3);
    const int aoff = g * 32 + awl;

    const uint32_t sbWB = smem_u32(smem + SM_WB);

    float acc[2][8][4];
    #pragma unroll
    for (int mi = 0; mi < 2; ++mi)
        #pragma unroll
        for (int ni = 0; ni < 8; ++ni)
            #pragma unroll
            for (int r = 0; r < 4; ++r) acc[mi][ni][r] = 0.f;

    // ============================ Layer 1 ================================
    const __half* w1i = g_w1i + c_w1i_off[node];
    #pragma unroll 1
    for (int c = 0; c < nnb; ++c) {
        if (c) __syncthreads();
        {   // W chunk image memcpy: 8192 halves = 16KB (128 thr x 8 iters)
            const __half* ws = w1i + c * 8192;
            #pragma unroll
            for (int i = 0; i < 8; ++i) {
                int idx = tid + i * 128;
                CP16(sbWB + idx * 16, ws + idx * 8);
            }
        }
        {   // X chunk: 64 rows x 64 cols f32 -> f16 pair-shuffled
            const int jo = c_nb[node][c] * 64;
            const float* xb = p.x + (size_t)m0 * 1344 + jo;
            #pragma unroll
            for (int i = 0; i < 2; ++i) {
                int v = tid + i * 128;
                int m = v >> 2, kt = v & 3;
                const float* s = xb + (size_t)m * 1344 + kt * 16;
                float4 A0 = *(const float4*)s;
                float4 A1 = *(const float4*)(s + 4);
                float4 A2 = *(const float4*)(s + 8);
                float4 A3 = *(const float4*)(s + 12);
                uint4 q0 = make_uint4(pkh2(A0.x, A0.y), pkh2(A2.x, A2.y),
                                      pkh2(A0.z, A0.w), pkh2(A2.z, A2.w));
                uint4 q1 = make_uint4(pkh2(A1.x, A1.y), pkh2(A3.x, A3.y),
                                      pkh2(A1.z, A1.w), pkh2(A3.z, A3.w));
                int r = m & 15, R = m >> 4;
                char* dst = smem + SM_XA + (R * 4 + kt) * 528 + r * 32;
                int sw = (r & 4) << 2;
                *(uint4*)(dst + sw) = q0;
                *(uint4*)(dst + (16 ^ sw)) = q1;
            }
        }
        CP_WAIT();
        __syncthreads();
        #pragma unroll
        for (int k16 = 0; k16 < 4; ++k16) {
            uint2 a[2][2];
            #pragma unroll
            for (int mi = 0; mi < 2; ++mi) {
                const char* ap = smem + SM_XA + ((wm * 2 + mi) * 4 + k16) * 528 + aoff;
                a[mi][0] = *(const uint2*)ap;
                a[mi][1] = *(const uint2*)(ap + 256);
            }
            #pragma unroll
            for (int ni = 0; ni < 8; ++ni) {
                const char* bp = smem + SM_WB + ((wn * 8 + ni) * 4 + k16) * 256 + aoff;
                uint2 b = *(const uint2*)bp;
                domma(acc[0][ni], a[0][0], a[0][1], b);
                domma(acc[1][ni], a[1][0], a[1][1], b);
            }
        }
    }

    // epilogue 1: bias + relu -> fp16 words into HA
    {
        const float* bp = p.b1[gi] + ki * 128;
        #pragma unroll
        for (int ni = 0; ni < 8; ++ni) {
            int col0 = wn * 64 + ni * 8 + 2 * t4;
            float2 bb = *(const float2*)(bp + col0);
            int kt = wn * 4 + (ni >> 1);
            int off = awl + ((ni & 1) << 2);
            #pragma unroll
            for (int mi = 0; mi < 2; ++mi) {
                char* base = smem + SM_HA + ((wm * 2 + mi) * 8 + kt) * 512 + g * 32 + off;
                *(uint32_t*)base = pkh2(fmaxf(acc[mi][ni][0] + bb.x, 0.f),
                                        fmaxf(acc[mi][ni][1] + bb.y, 0.f));
                *(uint32_t*)(base + 256) = pkh2(fmaxf(acc[mi][ni][2] + bb.x, 0.f),
                                                fmaxf(acc[mi][ni][3] + bb.y, 0.f));
                acc[mi][ni][0] = acc[mi][ni][1] = acc[mi][ni][2] = acc[mi][ni][3] = 0.f;
            }
        }
    }
    __syncthreads();

    // ============================ Layer 2 ================================
    const __half* w2i = g_w2i + node * 16384;
    #pragma unroll 1
    for (int c = 0; c < 2; ++c) {
        if (c) __syncthreads();
        {
            const __half* ws = w2i + c * 8192;
            #pragma unroll
            for (int i = 0; i < 8; ++i) {
                int idx = tid + i * 128;
                CP16(sbWB + idx * 16, ws + idx * 8);
            }
        }
        CP_WAIT();
        __syncthreads();
        #pragma unroll
        for (int k16 = 0; k16 < 4; ++k16) {
            uint2 a[2][2];
            #pragma unroll
            for (int mi = 0; mi < 2; ++mi) {
                const char* ap = smem + SM_HA +
                    ((wm * 2 + mi) * 8 + c * 4 + k16) * 512 + aoff;
                a[mi][0] = *(const uint2*)ap;
                a[mi][1] = *(const uint2*)(ap + 256);
            }
            #pragma unroll
            for (int ni = 0; ni < 8; ++ni) {
                const char* bp = smem + SM_WB + ((wn * 8 + ni) * 4 + k16) * 256 + aoff;
                uint2 b = *(const uint2*)bp;
                domma(acc[0][ni], a[0][0], a[0][1], b);
                domma(acc[1][ni], a[1][0], a[1][1], b);
            }
        }
    }
    __syncthreads();   // layer-2 HA reads done before in-place overwrite

    // epilogue 2: bias + relu -> HA (in place)
    {
        const float* bp = p.b2[gi] + ki * 128;
        #pragma unroll
        for (int ni = 0; ni < 8; ++ni) {
            int col0 = wn * 64 + ni * 8 + 2 * t4;
            float2 bb = *(const float2*)(bp + col0);
            int kt = wn * 4 + (ni >> 1);
            int off = awl + ((ni & 1) << 2);
            #pragma unroll
            for (int mi = 0; mi < 2; ++mi) {
                char* base = smem + SM_HA + ((wm * 2 + mi) * 8 + kt) * 512 + g * 32 + off;
                *(uint32_t*)base = pkh2(fmaxf(acc[mi][ni][0] + bb.x, 0.f),
                                        fmaxf(acc[mi][ni][1] + bb.y, 0.f));
                *(uint32_t*)(base + 256) = pkh2(fmaxf(acc[mi][ni][2] + bb.x, 0.f),
                                                fmaxf(acc[mi][ni][3] + bb.y, 0.f));
                acc[mi][ni][0] = acc[mi][ni][1] = acc[mi][ni][2] = acc[mi][ni][3] = 0.f;
            }
        }
    }
    __syncthreads();

    // ============================ Layer 3 ================================
    {   // W3 image: 64n x 128k = 16KB
        const __half* ws = g_w3i + node * 8192;
        #pragma unroll
        for (int i = 0; i < 8; ++i) {
            int idx = tid + i * 128;
            CP16(sbWB + idx * 16, ws + idx * 8);
        }
    }
    CP_WAIT();
    __syncthreads();

    #pragma unroll
    for (int k16 = 0; k16 < 8; ++k16) {
        uint2 a[2][2];
        #pragma unroll
        for (int mi = 0; mi < 2; ++mi) {
            const char* ap = smem + SM_HA + ((wm * 2 + mi) * 8 + k16) * 512 + aoff;
            a[mi][0] = *(const uint2*)ap;
            a[mi][1] = *(const uint2*)(ap + 256);
        }
        #pragma unroll
        for (int ni = 0; ni < 4; ++ni) {
            const char* bp = smem + SM_WB + ((wn * 4 + ni) * 8 + k16) * 256 + aoff;
            uint2 b = *(const uint2*)bp;
            domma(acc[0][ni], a[0][0], a[0][1], b);
            domma(acc[1][ni], a[1][0], a[1][1], b);
        }
    }

    // epilogue 3: bias, f32 STG.64 direct
    {
        const float* bp = p.b3[gi] + ki * 64;
        const int oj = c_out[node] * 64;
        #pragma unroll
        for (int ni = 0; ni < 4; ++ni) {
            int col0 = wn * 32 + ni * 8 + 2 * t4;
            float2 bb = *(const float2*)(bp + col0);
            #pragma unroll
            for (int mi = 0; mi < 2; ++mi) {
                size_t ro = (size_t)(m0 + wm * 32 + mi * 16 + g) * 1344 + oj + col0;
                *(float2*)(p.out + ro) =
                    make_float2(acc[mi][ni][0] + bb.x, acc[mi][ni][1] + bb.y);
                *(float2*)(p.out + ro + (size_t)8 * 1344) =
                    make_float2(acc[mi][ni][2] + bb.x, acc[mi][ni][3] + bb.y);
            }
        }
    }
}

// ------------------------------ launch -------------------------------------

extern "C" void kernel_launch(void* const* d_in, const int* in_sizes, int n_in,
                              void* d_out, int out_size) {
    (void)n_in; (void)out_size;
    Params p;
    p.x = (const float*)d_in[0];
    int idx = 1;
    for (int gi = 0; gi < 5; ++gi) {
        p.w1[gi] = (const float*)d_in[idx++];
        p.b1[gi] = (const float*)d_in[idx++];
        p.w2[gi] = (const float*)d_in[idx++];
        p.b2[gi] = (const float*)d_in[idx++];
        p.w3[gi] = (const float*)d_in[idx++];
        p.b3[gi] = (const float*)d_in[idx++];
    }
    p.out = (float*)d_out;

    const int B = in_sizes[0] / (21 * 64);

    prep_kernel<<<dim3(192, 21, 3), 256>>>(p);

    cudaFuncSetAttribute(mp13_kernel, cudaFuncAttributeMaxDynamicSharedMemorySize,
                         SMEM_TOTAL);
    dim3 grid(21, B / 64);
    mp13_kernel<<<grid, 128, SMEM_TOTAL>>>(p);
}